// round 2
// baseline (speedup 1.0000x reference)
#include <cuda_runtime.h>
#include <stdint.h>

#define OUTF 8192
#define INF  8192
#define GROUPS 256            // groups of 32 in-features (3 packed words each)
#define KS 64                 // split-K factor
#define GPB (GROUPS / KS)     // 4 groups per block
#define TPB 256
#define COLS_PER_THREAD 4
#define COLS_PER_BLOCK (TPB * COLS_PER_THREAD)   // 1024
#define NCB (OUTF / COLS_PER_BLOCK)              // 8
#define ROWSTRIDE4 (OUTF / 4)                    // uint4 row stride

// split-K partial dot products: partial[k][n] = sum over K-slice k of x*q
__device__ float g_partial[KS * OUTF];
__device__ float g_sumx;

// exact int3 -> float via magic number (no I2F): 0x4B000000|v == 2^23 + v
__device__ __forceinline__ float dq3(unsigned v) {
    return __uint_as_float(0x4B000000u | v) - 8388608.0f;
}

// unpack one GPTQ int3 triple (32 values) for one column, accumulate x·q
__device__ __forceinline__ float unpack_col(unsigned w0, unsigned w1, unsigned w2,
                                            const float* __restrict__ xr, float acc) {
#pragma unroll
    for (int j = 0; j < 10; j++)
        acc = fmaf(xr[j], dq3((w0 >> (3 * j)) & 7u), acc);
    acc = fmaf(xr[10], dq3(((w0 >> 30) & 3u) | ((w1 & 1u) << 2)), acc);
#pragma unroll
    for (int j = 0; j < 10; j++)
        acc = fmaf(xr[11 + j], dq3((w1 >> (3 * j + 1)) & 7u), acc);
    acc = fmaf(xr[21], dq3(((w1 >> 31) & 1u) | ((w2 & 3u) << 1)), acc);
#pragma unroll
    for (int j = 0; j < 10; j++)
        acc = fmaf(xr[22 + j], dq3((w2 >> (3 * j + 2)) & 7u), acc);
    return acc;
}

__global__ __launch_bounds__(TPB)
void q3_dot_kernel(const float* __restrict__ x, const unsigned* __restrict__ qw) {
    __shared__ float xs[GPB * 32];
    __shared__ float sred[TPB / 32];

    const int tid = threadIdx.x;
    const int gbase = blockIdx.y * GPB;      // first group of this K-slice
    const int kbase = gbase * 32;            // first in-feature

    // stage this K-slice of x into shared
    for (int i = tid; i < GPB * 32; i += TPB) xs[i] = x[kbase + i];

    // block (0,0) additionally computes sum(x) for the epilogue kernel
    if (blockIdx.x == 0 && blockIdx.y == 0) {
        const float4* __restrict__ x4 = (const float4*)x;
        float s = 0.f;
#pragma unroll
        for (int i = 0; i < INF / (4 * TPB); i++) {
            float4 v = x4[tid + TPB * i];
            s += (v.x + v.y) + (v.z + v.w);
        }
#pragma unroll
        for (int o = 16; o > 0; o >>= 1) s += __shfl_down_sync(0xffffffffu, s, o);
        if ((tid & 31) == 0) sred[tid >> 5] = s;
        __syncthreads();
        if (tid == 0) {
            float t = 0.f;
#pragma unroll
            for (int w = 0; w < TPB / 32; w++) t += sred[w];
            g_sumx = t;
        }
    }
    __syncthreads();

    const int c = blockIdx.x * COLS_PER_BLOCK + tid * COLS_PER_THREAD;
    const uint4* __restrict__ q4 = (const uint4*)qw;
    long base = (long)(gbase * 3) * ROWSTRIDE4 + (c >> 2);

    float a0 = 0.f, a1 = 0.f, a2 = 0.f, a3 = 0.f;

    // prologue load (group 0 of slice)
    uint4 cw0 = q4[base];
    uint4 cw1 = q4[base + ROWSTRIDE4];
    uint4 cw2 = q4[base + 2 * ROWSTRIDE4];

#pragma unroll 1
    for (int g = 0; g < GPB; g++) {
        uint4 nw0, nw1, nw2;
        if (g + 1 < GPB) {                   // prefetch next group while computing
            long nb = base + (long)(3 * (g + 1)) * ROWSTRIDE4;
            nw0 = q4[nb];
            nw1 = q4[nb + ROWSTRIDE4];
            nw2 = q4[nb + 2 * ROWSTRIDE4];
        }
        // pull this group's 32 x values into registers (broadcast LDS, reused 4x)
        float xr[32];
        const float* xp = &xs[g * 32];
#pragma unroll
        for (int j = 0; j < 32; j++) xr[j] = xp[j];

        a0 = unpack_col(cw0.x, cw1.x, cw2.x, xr, a0);
        a1 = unpack_col(cw0.y, cw1.y, cw2.y, xr, a1);
        a2 = unpack_col(cw0.z, cw1.z, cw2.z, xr, a2);
        a3 = unpack_col(cw0.w, cw1.w, cw2.w, xr, a3);

        cw0 = nw0; cw1 = nw1; cw2 = nw2;
    }

    float4 o = make_float4(a0, a1, a2, a3);
    *(float4*)&g_partial[blockIdx.y * OUTF + c] = o;
}

#define RTPB 128
__global__ __launch_bounds__(RTPB)
void q3_reduce_kernel(const float* __restrict__ scales,
                      const float* __restrict__ zeros,
                      const float* __restrict__ bias,
                      float* __restrict__ y) {
    const int n = blockIdx.x * RTPB + threadIdx.x;

    // 4 independent accumulator chains (fixed order -> deterministic)
    float a0 = 0.f, a1 = 0.f, a2 = 0.f, a3 = 0.f;
#pragma unroll
    for (int k = 0; k < KS; k += 4) {
        a0 += g_partial[(k + 0) * OUTF + n];
        a1 += g_partial[(k + 1) * OUTF + n];
        a2 += g_partial[(k + 2) * OUTF + n];
        a3 += g_partial[(k + 3) * OUTF + n];
    }
    const float acc = (a0 + a1) + (a2 + a3);

    y[n] = scales[n] * acc - zeros[n] * g_sumx + bias[n];
}

extern "C" void kernel_launch(void* const* d_in, const int* in_sizes, int n_in,
                              void* d_out, int out_size) {
    const float*    x      = (const float*)d_in[0];
    const unsigned* qw     = (const unsigned*)d_in[1];   // int32 bits -> uint32
    const float*    scales = (const float*)d_in[2];
    const float*    zeros  = (const float*)d_in[3];
    const float*    bias   = (const float*)d_in[4];
    float*          y      = (float*)d_out;

    dim3 grid(NCB, KS);
    q3_dot_kernel<<<grid, TPB>>>(x, qw);
    q3_reduce_kernel<<<OUTF / RTPB, RTPB>>>(scales, zeros, bias, y);
}

// round 3
// speedup vs baseline: 1.4266x; 1.4266x over previous
#include <cuda_runtime.h>
#include <stdint.h>

#define OUTF 8192
#define INF  8192
#define GROUPS 256            // groups of 32 in-features (3 packed words each)
#define KS 32                 // split-K factor
#define GPB (GROUPS / KS)     // 8 groups per block
#define TPB 128
#define COLS_PER_THREAD 4
#define COLS_PER_BLOCK (TPB * COLS_PER_THREAD)   // 512
#define NCB (OUTF / COLS_PER_BLOCK)              // 16
#define ROWSTRIDE4 (OUTF / 4)                    // uint4 row stride

// split-K partial dot products: partial[k][n] = sum over K-slice k of x*q
__device__ float g_partial[KS * OUTF];
// per-stripe completion counters (zero-initialized; reducer resets to 0 each launch)
__device__ int g_count[NCB];

// exact int3 -> float via magic number (no I2F): 0x4B000000|v == 2^23 + v
__device__ __forceinline__ float dq3(unsigned v) {
    return __uint_as_float(0x4B000000u | v) - 8388608.0f;
}

// unpack one GPTQ int3 triple (32 values) for one column, accumulate x·q
__device__ __forceinline__ float unpack_col(unsigned w0, unsigned w1, unsigned w2,
                                            const float* __restrict__ xr, float acc) {
#pragma unroll
    for (int j = 0; j < 10; j++)
        acc = fmaf(xr[j], dq3((w0 >> (3 * j)) & 7u), acc);
    acc = fmaf(xr[10], dq3(((w0 >> 30) & 3u) | ((w1 & 1u) << 2)), acc);
#pragma unroll
    for (int j = 0; j < 10; j++)
        acc = fmaf(xr[11 + j], dq3((w1 >> (3 * j + 1)) & 7u), acc);
    acc = fmaf(xr[21], dq3(((w1 >> 31) & 1u) | ((w2 & 3u) << 1)), acc);
#pragma unroll
    for (int j = 0; j < 10; j++)
        acc = fmaf(xr[22 + j], dq3((w2 >> (3 * j + 2)) & 7u), acc);
    return acc;
}

__global__ __launch_bounds__(TPB)
void q3_fused_kernel(const float* __restrict__ x, const unsigned* __restrict__ qw,
                     const float* __restrict__ scales,
                     const float* __restrict__ zeros,
                     const float* __restrict__ bias,
                     float* __restrict__ y) {
    __shared__ float xs[GPB * 32];
    __shared__ float wsum[TPB / 32];
    __shared__ int amLast;

    const int tid = threadIdx.x;
    const int gbase = blockIdx.y * GPB;      // first group of this K-slice
    const int kbase = gbase * 32;            // first in-feature

    // stage this K-slice of x into shared
    for (int i = tid; i < GPB * 32; i += TPB) xs[i] = x[kbase + i];
    __syncthreads();

    const int c = blockIdx.x * COLS_PER_BLOCK + tid * COLS_PER_THREAD;
    const uint4* __restrict__ q4 = (const uint4*)qw;
    long base = (long)(gbase * 3) * ROWSTRIDE4 + (c >> 2);

    float a0 = 0.f, a1 = 0.f, a2 = 0.f, a3 = 0.f;

    // prologue load (group 0 of slice)
    uint4 cw0 = q4[base];
    uint4 cw1 = q4[base + ROWSTRIDE4];
    uint4 cw2 = q4[base + 2 * ROWSTRIDE4];

#pragma unroll 1
    for (int g = 0; g < GPB; g++) {
        uint4 nw0, nw1, nw2;
        if (g + 1 < GPB) {                   // prefetch next group while computing
            long nb = base + (long)(3 * (g + 1)) * ROWSTRIDE4;
            nw0 = q4[nb];
            nw1 = q4[nb + ROWSTRIDE4];
            nw2 = q4[nb + 2 * ROWSTRIDE4];
        }
        // pull this group's 32 x values into registers (broadcast LDS, reused 4x)
        float xr[32];
        const float* xp = &xs[g * 32];
#pragma unroll
        for (int j = 0; j < 32; j++) xr[j] = xp[j];

        a0 = unpack_col(cw0.x, cw1.x, cw2.x, xr, a0);
        a1 = unpack_col(cw0.y, cw1.y, cw2.y, xr, a1);
        a2 = unpack_col(cw0.z, cw1.z, cw2.z, xr, a2);
        a3 = unpack_col(cw0.w, cw1.w, cw2.w, xr, a3);

        cw0 = nw0; cw1 = nw1; cw2 = nw2;
    }

    *(float4*)&g_partial[blockIdx.y * OUTF + c] = make_float4(a0, a1, a2, a3);

    // ---- last-block-done tail reduction for this column stripe ----
    __threadfence();
    if (tid == 0) {
        int old = atomicAdd(&g_count[blockIdx.x], 1);
        amLast = (old == KS - 1);
    }
    __syncthreads();

    if (amLast) {
        // block-wide sum of x (fixed order -> deterministic, same in every stripe)
        const float4* __restrict__ x4 = (const float4*)x;
        float s = 0.f;
#pragma unroll
        for (int i = 0; i < INF / (4 * TPB); i++) {
            float4 v = x4[tid + TPB * i];
            s += (v.x + v.y) + (v.z + v.w);
        }
#pragma unroll
        for (int o = 16; o > 0; o >>= 1) s += __shfl_down_sync(0xffffffffu, s, o);
        if ((tid & 31) == 0) wsum[tid >> 5] = s;
        __syncthreads();
        const float sumx = (wsum[0] + wsum[1]) + (wsum[2] + wsum[3]);

        // reduce the 32 split-K partials for this stripe in fixed k-order
        float r0 = 0.f, r1 = 0.f, r2 = 0.f, r3 = 0.f;
#pragma unroll
        for (int k = 0; k < KS; k++) {
            float4 p = *(const float4*)&g_partial[k * OUTF + c];
            r0 += p.x; r1 += p.y; r2 += p.z; r3 += p.w;
        }

        float4 sc = *(const float4*)&scales[c];
        float4 zr = *(const float4*)&zeros[c];
        float4 bi = *(const float4*)&bias[c];
        float4 o;
        o.x = sc.x * r0 - zr.x * sumx + bi.x;
        o.y = sc.y * r1 - zr.y * sumx + bi.y;
        o.z = sc.z * r2 - zr.z * sumx + bi.z;
        o.w = sc.w * r3 - zr.w * sumx + bi.w;
        *(float4*)&y[c] = o;

        if (tid == 0) g_count[blockIdx.x] = 0;   // reset for next launch/replay
    }
}

extern "C" void kernel_launch(void* const* d_in, const int* in_sizes, int n_in,
                              void* d_out, int out_size) {
    const float*    x      = (const float*)d_in[0];
    const unsigned* qw     = (const unsigned*)d_in[1];   // int32 bits -> uint32
    const float*    scales = (const float*)d_in[2];
    const float*    zeros  = (const float*)d_in[3];
    const float*    bias   = (const float*)d_in[4];
    float*          y      = (float*)d_out;

    dim3 grid(NCB, KS);
    q3_fused_kernel<<<grid, TPB>>>(x, qw, scales, zeros, bias, y);
}

// round 4
// speedup vs baseline: 1.7597x; 1.2335x over previous
#include <cuda_runtime.h>
#include <stdint.h>

#define OUTF 8192
#define INF  8192
#define GROUPS 256            // groups of 32 in-features (3 packed words each)
#define KS 32                 // split-K factor
#define GPB (GROUPS / KS)     // 8 groups per block
#define TPB 128
#define COLS_PER_THREAD 4
#define COLS_PER_BLOCK (TPB * COLS_PER_THREAD)   // 512
#define NCB (OUTF / COLS_PER_BLOCK)              // 16
#define ROWSTRIDE4 (OUTF / 4)                    // uint4 row stride

// parity mask: value indices (mod 32) that are the "hi" member of an extraction
// pair; their x is pre-scaled by 1/8 at staging (exact power of two).
// hi positions: {1,3,5,7,9, 12,14,16,18,20, 23,25,27,29,31}
#define HI_MASK 0xAA9552AAu

// split-K partial dot products: partial[k][n] = sum over K-slice k of x*q
__device__ float g_partial[KS * OUTF];
// per-stripe completion counters (zero-init; reducer resets to 0 each launch)
__device__ int g_count[NCB];

// (s & 7) | 0x4B000000 in ONE LOP3, then exact float convert: 2^23 + v
__device__ __forceinline__ float dq_lo(unsigned s) {
    unsigned r;
    asm("lop3.b32 %0, %1, 0x7, 0x4B000000, 0xEA;" : "=r"(r) : "r"(s));
    return __uint_as_float(r) - 8388608.0f;          // = v
}
// (s & 0x38) | 0x4B000000 -> 2^23 + 8*v ; caller's x is pre-scaled by 1/8
__device__ __forceinline__ float dq_hi(unsigned s) {
    unsigned r;
    asm("lop3.b32 %0, %1, 0x38, 0x4B000000, 0xEA;" : "=r"(r) : "r"(s));
    return __uint_as_float(r) - 8388608.0f;          // = 8*v
}
__device__ __forceinline__ float dq3(unsigned v) {
    return __uint_as_float(0x4B000000u | v) - 8388608.0f;
}

// unpack one GPTQ int3 triple (32 values) for one column, accumulate x·q.
// xr[] must be parity-scaled per HI_MASK.
__device__ __forceinline__ float unpack_col(unsigned w0, unsigned w1, unsigned w2,
                                            const float* __restrict__ xr, float acc) {
#pragma unroll
    for (int t = 0; t < 5; t++) {          // v0..v9 at offsets 0,3,...,27
        unsigned s = w0 >> (6 * t);
        acc = fmaf(xr[2 * t],     dq_lo(s), acc);
        acc = fmaf(xr[2 * t + 1], dq_hi(s), acc);
    }
    acc = fmaf(xr[10], dq3(((w0 >> 30) & 3u) | ((w1 & 1u) << 2)), acc);
#pragma unroll
    for (int t = 0; t < 5; t++) {          // v11..v20 at offsets 1,4,...,28
        unsigned s = w1 >> (6 * t + 1);
        acc = fmaf(xr[11 + 2 * t], dq_lo(s), acc);
        acc = fmaf(xr[12 + 2 * t], dq_hi(s), acc);
    }
    acc = fmaf(xr[21], dq3(((w1 >> 31) & 1u) | ((w2 & 3u) << 1)), acc);
#pragma unroll
    for (int t = 0; t < 5; t++) {          // v22..v31 at offsets 2,5,...,29
        unsigned s = w2 >> (6 * t + 2);
        acc = fmaf(xr[22 + 2 * t], dq_lo(s), acc);
        acc = fmaf(xr[23 + 2 * t], dq_hi(s), acc);
    }
    return acc;
}

__global__ __launch_bounds__(TPB)
void q3_fused_kernel(const float* __restrict__ x, const unsigned* __restrict__ qw,
                     const float* __restrict__ scales,
                     const float* __restrict__ zeros,
                     const float* __restrict__ bias,
                     float* __restrict__ y) {
    __shared__ float xs[GPB * 32];
    __shared__ float wsum[TPB / 32];
    __shared__ int amLast;

    const int tid = threadIdx.x;
    const int gbase = blockIdx.y * GPB;      // first group of this K-slice
    const int kbase = gbase * 32;            // first in-feature

    // stage this K-slice of x into shared, parity-scaled (exact /8 for hi slots)
    for (int i = tid; i < GPB * 32; i += TPB) {
        float v = x[kbase + i];
        if ((HI_MASK >> (i & 31)) & 1u) v *= 0.125f;
        xs[i] = v;
    }
    __syncthreads();

    const int c = blockIdx.x * COLS_PER_BLOCK + tid * COLS_PER_THREAD;
    const uint4* __restrict__ q4 = (const uint4*)qw;
    long base = (long)(gbase * 3) * ROWSTRIDE4 + (c >> 2);

    float a0 = 0.f, a1 = 0.f, a2 = 0.f, a3 = 0.f;

    // prologue load (group 0 of slice)
    uint4 cw0 = q4[base];
    uint4 cw1 = q4[base + ROWSTRIDE4];
    uint4 cw2 = q4[base + 2 * ROWSTRIDE4];

#pragma unroll 1
    for (int g = 0; g < GPB; g++) {
        uint4 nw0, nw1, nw2;
        if (g + 1 < GPB) {                   // prefetch next group while computing
            long nb = base + (long)(3 * (g + 1)) * ROWSTRIDE4;
            nw0 = q4[nb];
            nw1 = q4[nb + ROWSTRIDE4];
            nw2 = q4[nb + 2 * ROWSTRIDE4];
        }
        // pull this group's 32 (pre-scaled) x values into registers
        float xr[32];
        const float* xp = &xs[g * 32];
#pragma unroll
        for (int j = 0; j < 32; j++) xr[j] = xp[j];

        a0 = unpack_col(cw0.x, cw1.x, cw2.x, xr, a0);
        a1 = unpack_col(cw0.y, cw1.y, cw2.y, xr, a1);
        a2 = unpack_col(cw0.z, cw1.z, cw2.z, xr, a2);
        a3 = unpack_col(cw0.w, cw1.w, cw2.w, xr, a3);

        cw0 = nw0; cw1 = nw1; cw2 = nw2;
    }

    *(float4*)&g_partial[blockIdx.y * OUTF + c] = make_float4(a0, a1, a2, a3);

    // ---- last-block-done tail reduction for this column stripe ----
    __threadfence();
    if (tid == 0) {
        int old = atomicAdd(&g_count[blockIdx.x], 1);
        amLast = (old == KS - 1);
    }
    __syncthreads();

    if (amLast) {
        // block-wide sum of x (fixed order -> deterministic, same in every stripe)
        const float4* __restrict__ x4 = (const float4*)x;
        float s = 0.f;
#pragma unroll
        for (int i = 0; i < INF / (4 * TPB); i++) {
            float4 v = x4[tid + TPB * i];
            s += (v.x + v.y) + (v.z + v.w);
        }
#pragma unroll
        for (int o = 16; o > 0; o >>= 1) s += __shfl_down_sync(0xffffffffu, s, o);
        if ((tid & 31) == 0) wsum[tid >> 5] = s;
        __syncthreads();
        const float sumx = (wsum[0] + wsum[1]) + (wsum[2] + wsum[3]);

        // reduce the 32 split-K partials for this stripe in fixed k-order
        float r0 = 0.f, r1 = 0.f, r2 = 0.f, r3 = 0.f;
#pragma unroll
        for (int k = 0; k < KS; k++) {
            float4 p = *(const float4*)&g_partial[k * OUTF + c];
            r0 += p.x; r1 += p.y; r2 += p.z; r3 += p.w;
        }

        float4 sc = *(const float4*)&scales[c];
        float4 zr = *(const float4*)&zeros[c];
        float4 bi = *(const float4*)&bias[c];
        float4 o;
        o.x = sc.x * r0 - zr.x * sumx + bi.x;
        o.y = sc.y * r1 - zr.y * sumx + bi.y;
        o.z = sc.z * r2 - zr.z * sumx + bi.z;
        o.w = sc.w * r3 - zr.w * sumx + bi.w;
        *(float4*)&y[c] = o;

        if (tid == 0) g_count[blockIdx.x] = 0;   // reset for next launch/replay
    }
}

extern "C" void kernel_launch(void* const* d_in, const int* in_sizes, int n_in,
                              void* d_out, int out_size) {
    const float*    x      = (const float*)d_in[0];
    const unsigned* qw     = (const unsigned*)d_in[1];   // int32 bits -> uint32
    const float*    scales = (const float*)d_in[2];
    const float*    zeros  = (const float*)d_in[3];
    const float*    bias   = (const float*)d_in[4];
    float*          y      = (float*)d_out;

    dim3 grid(NCB, KS);
    q3_fused_kernel<<<grid, TPB>>>(x, qw, scales, zeros, bias, y);
}

// round 5
// speedup vs baseline: 1.9403x; 1.1026x over previous
#include <cuda_runtime.h>
#include <stdint.h>

#define OUTF 8192
#define INF  8192
#define GROUPS 256            // groups of 32 in-features (3 packed words each)
#define KS 32                 // split-K factor
#define GPB (GROUPS / KS)     // 8 groups per block
#define TPB 128
#define COLS_PER_THREAD 4
#define COLS_PER_BLOCK (TPB * COLS_PER_THREAD)   // 512
#define NCB (OUTF / COLS_PER_BLOCK)              // 16
#define ROWSTRIDE4 (OUTF / 4)                    // uint4 row stride

// parity mask over SOURCE index (mod 32): "hi" member of an extraction pair,
// whose x is pre-scaled by 1/8 at staging (exact power of two).
#define HI_MASK 0xAA9552AAu

// split-K partial dot products: partial[k][n] = sum over K-slice k of x*q
__device__ float g_partial[KS * OUTF];
// per-stripe completion counters (zero-init; reducer resets to 0 each launch)
__device__ int g_count[NCB];

__device__ __forceinline__ float dq3(unsigned v) {
    return __uint_as_float(0x4B000000u | v) - 8388608.0f;
}

// One extraction pair, fully packed:
//   lo = (s & 7)  | 0x4B000000   -> 2^23 + v_lo
//   hi = (s & 56) | 0x4B000000   -> 2^23 + 8*v_hi   (x_hi pre-scaled by 1/8)
// then one ADD2 (de-bias both lanes) + one FFMA2 (both products into acc).
__device__ __forceinline__ void dqpair(unsigned s, unsigned long long xp,
                                       unsigned long long nb, unsigned long long &acc) {
    unsigned lo, hi;
    asm("lop3.b32 %0, %1, 0x7, 0x4B000000, 0xEA;" : "=r"(lo) : "r"(s));
    asm("lop3.b32 %0, %1, 0x38, 0x4B000000, 0xEA;" : "=r"(hi) : "r"(s));
    unsigned long long f;
    asm("mov.b64 %0, {%1, %2};" : "=l"(f) : "r"(lo), "r"(hi));
    asm("add.rn.f32x2 %0, %1, %2;" : "=l"(f) : "l"(f), "l"(nb));
    asm("fma.rn.f32x2 %0, %1, %2, %3;" : "=l"(acc) : "l"(xp), "l"(f), "l"(acc));
}

// unpack one GPTQ int3 triple (32 values) for one column.
// xpr: 15 packed x pairs (permuted layout); xb10/xb21: boundary x values.
__device__ __forceinline__ void unpack_col_p(unsigned w0, unsigned w1, unsigned w2,
                                             const unsigned long long* __restrict__ xpr,
                                             float xb10, float xb21,
                                             unsigned long long nb,
                                             unsigned long long &acc, float &accs) {
#pragma unroll
    for (int t = 0; t < 5; t++)            // v0..v9
        dqpair(w0 >> (6 * t), xpr[t], nb, acc);
    accs = fmaf(xb10, dq3(((w0 >> 30) & 3u) | ((w1 & 1u) << 2)), accs);
#pragma unroll
    for (int t = 0; t < 5; t++)            // v11..v20
        dqpair(w1 >> (6 * t + 1), xpr[5 + t], nb, acc);
    accs = fmaf(xb21, dq3(((w1 >> 31) & 1u) | ((w2 & 3u) << 1)), accs);
#pragma unroll
    for (int t = 0; t < 5; t++)            // v22..v31
        dqpair(w2 >> (6 * t + 2), xpr[10 + t], nb, acc);
}

__global__ __launch_bounds__(TPB)
void q3_fused_kernel(const float* __restrict__ x, const unsigned* __restrict__ qw,
                     const float* __restrict__ scales,
                     const float* __restrict__ zeros,
                     const float* __restrict__ bias,
                     float* __restrict__ y) {
    __shared__ __align__(16) float xs[GPB * 32];
    __shared__ float wsum[TPB / 32];
    __shared__ int amLast;

    const int tid = threadIdx.x;
    const int gbase = blockIdx.y * GPB;      // first group of this K-slice
    const int kbase = gbase * 32;            // first in-feature

    // stage this K-slice of x into shared: parity-scaled AND permuted so each
    // extraction pair occupies an aligned 8-byte slot.
    //   src 0..9   -> slots 0..9      (w0 pairs)
    //   src 10     -> slot 30         (boundary v10)
    //   src 11..20 -> slots 10..19    (w1 pairs)
    //   src 21     -> slot 31         (boundary v21)
    //   src 22..31 -> slots 20..29    (w2 pairs)
    for (int i = tid; i < GPB * 32; i += TPB) {
        const int s32 = i & 31, g = i >> 5;
        float v = x[kbase + i];
        if ((HI_MASK >> s32) & 1u) v *= 0.125f;
        int d;
        if (s32 == 10)      d = 30;
        else if (s32 == 21) d = 31;
        else if (s32 < 10)  d = s32;
        else if (s32 < 21)  d = s32 - 1;
        else                d = s32 - 2;
        xs[g * 32 + d] = v;
    }
    __syncthreads();

    const int c = blockIdx.x * COLS_PER_BLOCK + tid * COLS_PER_THREAD;
    const uint4* __restrict__ q4 = (const uint4*)qw;
    long base = (long)(gbase * 3) * ROWSTRIDE4 + (c >> 2);

    unsigned long long a0 = 0ull, a1 = 0ull, a2 = 0ull, a3 = 0ull;   // packed (f32,f32)
    float s0 = 0.f, s1 = 0.f, s2 = 0.f, s3 = 0.f;                    // boundary accs
    const unsigned long long nb = 0xCB000000CB000000ull;             // (-2^23, -2^23)

    // prologue load (group 0 of slice)
    uint4 cw0 = q4[base];
    uint4 cw1 = q4[base + ROWSTRIDE4];
    uint4 cw2 = q4[base + 2 * ROWSTRIDE4];

#pragma unroll 1
    for (int g = 0; g < GPB; g++) {
        uint4 nw0, nw1, nw2;
        if (g + 1 < GPB) {                   // prefetch next group while computing
            long nbs = base + (long)(3 * (g + 1)) * ROWSTRIDE4;
            nw0 = q4[nbs];
            nw1 = q4[nbs + ROWSTRIDE4];
            nw2 = q4[nbs + 2 * ROWSTRIDE4];
        }
        // pull this group's 15 packed x pairs + 2 boundary x into registers
        const unsigned long long* __restrict__ xp =
            (const unsigned long long*)&xs[g * 32];
        unsigned long long xpr[15];
#pragma unroll
        for (int t = 0; t < 15; t++) xpr[t] = xp[t];
        const float xb10 = xs[g * 32 + 30];
        const float xb21 = xs[g * 32 + 31];

        unpack_col_p(cw0.x, cw1.x, cw2.x, xpr, xb10, xb21, nb, a0, s0);
        unpack_col_p(cw0.y, cw1.y, cw2.y, xpr, xb10, xb21, nb, a1, s1);
        unpack_col_p(cw0.z, cw1.z, cw2.z, xpr, xb10, xb21, nb, a2, s2);
        unpack_col_p(cw0.w, cw1.w, cw2.w, xpr, xb10, xb21, nb, a3, s3);

        cw0 = nw0; cw1 = nw1; cw2 = nw2;
    }

    // collapse packed lanes + boundary acc (fixed order -> deterministic)
    union { unsigned long long u; float2 f; } c0, c1, c2, c3;
    c0.u = a0; c1.u = a1; c2.u = a2; c3.u = a3;
    float4 o;
    o.x = (c0.f.x + c0.f.y) + s0;
    o.y = (c1.f.x + c1.f.y) + s1;
    o.z = (c2.f.x + c2.f.y) + s2;
    o.w = (c3.f.x + c3.f.y) + s3;
    *(float4*)&g_partial[blockIdx.y * OUTF + c] = o;

    // ---- last-block-done tail reduction for this column stripe ----
    __threadfence();
    if (tid == 0) {
        int old = atomicAdd(&g_count[blockIdx.x], 1);
        amLast = (old == KS - 1);
    }
    __syncthreads();

    if (amLast) {
        // block-wide sum of x (fixed order -> deterministic, same in every stripe)
        const float4* __restrict__ x4 = (const float4*)x;
        float s = 0.f;
#pragma unroll
        for (int i = 0; i < INF / (4 * TPB); i++) {
            float4 v = x4[tid + TPB * i];
            s += (v.x + v.y) + (v.z + v.w);
        }
#pragma unroll
        for (int o2 = 16; o2 > 0; o2 >>= 1) s += __shfl_down_sync(0xffffffffu, s, o2);
        if ((tid & 31) == 0) wsum[tid >> 5] = s;
        __syncthreads();
        const float sumx = (wsum[0] + wsum[1]) + (wsum[2] + wsum[3]);

        // reduce the 32 split-K partials for this stripe in fixed k-order
        float r0 = 0.f, r1 = 0.f, r2 = 0.f, r3 = 0.f;
#pragma unroll
        for (int k = 0; k < KS; k++) {
            float4 p = *(const float4*)&g_partial[k * OUTF + c];
            r0 += p.x; r1 += p.y; r2 += p.z; r3 += p.w;
        }

        float4 sc = *(const float4*)&scales[c];
        float4 zr = *(const float4*)&zeros[c];
        float4 bi = *(const float4*)&bias[c];
        float4 oy;
        oy.x = sc.x * r0 - zr.x * sumx + bi.x;
        oy.y = sc.y * r1 - zr.y * sumx + bi.y;
        oy.z = sc.z * r2 - zr.z * sumx + bi.z;
        oy.w = sc.w * r3 - zr.w * sumx + bi.w;
        *(float4*)&y[c] = oy;

        if (tid == 0) g_count[blockIdx.x] = 0;   // reset for next launch/replay
    }
}

extern "C" void kernel_launch(void* const* d_in, const int* in_sizes, int n_in,
                              void* d_out, int out_size) {
    const float*    x      = (const float*)d_in[0];
    const unsigned* qw     = (const unsigned*)d_in[1];   // int32 bits -> uint32
    const float*    scales = (const float*)d_in[2];
    const float*    zeros  = (const float*)d_in[3];
    const float*    bias   = (const float*)d_in[4];
    float*          y      = (float*)d_out;

    dim3 grid(NCB, KS);
    q3_fused_kernel<<<grid, TPB>>>(x, qw, scales, zeros, bias, y);
}